// round 3
// baseline (speedup 1.0000x reference)
#include <cuda_runtime.h>
#include <cstdint>

#define DI __device__ __forceinline__

static constexpr int NN  = 8192;
static constexpr int DIM = 256;

// ---------------- scratch (device globals; allocation forbidden) -----------
__device__ __align__(1024) float g_dis[NN];        // rsqrt(1 + rowsum(adj))
__device__ __align__(1024) float g_Mt[DIM * NN];   // M^T [n][j], tf32-rounded
__device__ __align__(1024) float g_Wt[DIM * DIM];  // W^T [n][k], tf32-rounded

// ---------------- helpers ----------------
DI uint32_t smem_u32(const void* p) {
    uint32_t a;
    asm("{ .reg .u64 t; cvta.to.shared.u64 t, %1; cvt.u32.u64 %0, t; }" : "=r"(a) : "l"(p));
    return a;
}
DI void cp16(uint32_t s, const void* g) {
    asm volatile("cp.async.cg.shared.global [%0], [%1], 16;" :: "r"(s), "l"(g) : "memory");
}
DI void cp_commit() { asm volatile("cp.async.commit_group;" ::: "memory"); }
template <int N> DI void cp_wait() {
    asm volatile("cp.async.wait_group %0;" :: "n"(N) : "memory");
}
DI uint32_t lds32(uint32_t a) {
    uint32_t v;
    asm volatile("ld.shared.b32 %0, [%1];" : "=r"(v) : "r"(a));
    return v;
}
DI uint32_t rna_tf32_u(uint32_t x) {
    uint32_t r;
    asm("cvt.rna.tf32.f32 %0, %1;" : "=r"(r) : "f"(__uint_as_float(x)));
    return r;
}
DI float rna_tf32(float x) {
    uint32_t r;
    asm("cvt.rna.tf32.f32 %0, %1;" : "=r"(r) : "f"(x));
    return __uint_as_float(r);
}
DI void mma_tf32(float* d, const uint32_t* a, const uint32_t* b) {
    asm volatile(
        "mma.sync.aligned.m16n8k8.row.col.f32.tf32.tf32.f32 "
        "{%0,%1,%2,%3}, {%4,%5,%6,%7}, {%8,%9}, {%0,%1,%2,%3};"
        : "+f"(d[0]), "+f"(d[1]), "+f"(d[2]), "+f"(d[3])
        : "r"(a[0]), "r"(a[1]), "r"(a[2]), "r"(a[3]), "r"(b[0]), "r"(b[1]));
}
DI uint32_t sw128(uint32_t off) { return off ^ ((off >> 3) & 0x70); }

// ---------------- SMEM layout ----------------
static constexpr int NST     = 4;
static constexpr int T_BYTES = 128 * 128;         // 128 rows x 32 fp32 (128B rows)
static constexpr int STAGE   = 2 * T_BYTES;       // A tile + B tile = 32 KB
static constexpr int DSMEM   = NST * STAGE;       // 128 KB

// ---------------- degree: g_dis[i] = rsqrt(1 + sum_j adj[i][j]) ------------
__global__ void __launch_bounds__(256) degree_kernel(const float* __restrict__ adj) {
    int i = blockIdx.x;
    const float4* row = reinterpret_cast<const float4*>(adj + (size_t)i * NN);
    float s = 0.f;
    for (int t = threadIdx.x; t < NN / 4; t += 256) {
        float4 v = row[t];
        s += (v.x + v.y) + (v.z + v.w);
    }
    for (int off = 16; off > 0; off >>= 1) s += __shfl_xor_sync(0xFFFFFFFFu, s, off);
    __shared__ float ws[8];
    if ((threadIdx.x & 31) == 0) ws[threadIdx.x >> 5] = s;
    __syncthreads();
    if (threadIdx.x == 0) {
        float t = 0.f;
        #pragma unroll
        for (int k = 0; k < 8; k++) t += ws[k];
        g_dis[i] = rsqrtf(t + 1.0f);
    }
}

// ---------------- prep: W^T rounded to tf32 --------------------------------
__global__ void __launch_bounds__(256) prep_w_kernel(const float* __restrict__ W) {
    int n = blockIdx.x, k = threadIdx.x;
    g_Wt[n * DIM + k] = rna_tf32(W[k * DIM + n]);
}

// ---------------- tf32 mma.sync GEMM: C[128x128] = A[128xK] @ B[128xK]^T ---
// EPI=0: A=x (lda=256, KT=8),   B=g_Wt.  C -> g_Mt[n][j] = rna(dis_j * acc)
// EPI=1: A=adj (lda=8192, KT=256), B=g_Mt. C -> out = relu(dis_i*(acc+Mt[n][i])+b[n])
template <int EPI>
__global__ void __launch_bounds__(256, 1)
gemm_k(const float* __restrict__ A, int lda, int KT,
       const float* __restrict__ bias, float* __restrict__ out) {
    const float* __restrict__ B = EPI ? (const float*)g_Mt : (const float*)g_Wt;
    const int ldb = EPI ? NN : DIM;

    extern __shared__ char smem[];
    const uint32_t sb = smem_u32(smem);
    const int tid = threadIdx.x, lane = tid & 31, wid = tid >> 5;
    const int wm = wid & 3, wn = wid >> 2;          // warp grid 4(M) x 2(N)
    const int mt = blockIdx.x, nt = blockIdx.y;
    const size_t mrow0 = (size_t)mt * 128;
    const size_t nrow0 = (size_t)nt * 128;

    // per-thread cp.async source/dest precompute: 8 chunks (4 A, 4 B)
    // chunk c in 0..1023 per tile: row=c>>3, seg=c&7
    const int c0 = tid;                              // + q*256

    float acc[2][8][4];
    #pragma unroll
    for (int mi = 0; mi < 2; mi++)
        #pragma unroll
        for (int ni = 0; ni < 8; ni++)
            #pragma unroll
            for (int r = 0; r < 4; r++) acc[mi][ni][r] = 0.f;

    auto load_stage = [&](int kt) {
        const int s = kt & (NST - 1);
        const uint32_t stA = sb + s * STAGE;
        const uint32_t stB = stA + T_BYTES;
        const int k0 = kt * 32;
        #pragma unroll
        for (int q = 0; q < 4; q++) {
            int c = q * 256 + c0, row = c >> 3, seg = c & 7;
            cp16(stA + sw128((uint32_t)(row * 128 + seg * 16)),
                 A + (mrow0 + row) * (size_t)lda + k0 + seg * 4);
        }
        #pragma unroll
        for (int q = 0; q < 4; q++) {
            int c = q * 256 + c0, row = c >> 3, seg = c & 7;
            cp16(stB + sw128((uint32_t)(row * 128 + seg * 16)),
                 B + (nrow0 + row) * (size_t)ldb + k0 + seg * 4);
        }
        cp_commit();
    };

    // prologue: 3 stages in flight
    for (int p = 0; p < NST - 1 && p < KT; p++) load_stage(p);

    // fragment LDS base offsets
    const int arow_base = wm * 32 + (lane >> 2);     // + mi*16, +8
    const int brow_base = wn * 64 + (lane >> 2);     // + ni*8
    const int kcol = lane & 3;                       // + ks*8, +4

    for (int kt = 0; kt < KT; kt++) {
        cp_wait<NST - 2>();
        __syncthreads();
        const int s = kt & (NST - 1);
        const uint32_t stA = sb + s * STAGE;
        const uint32_t stB = stA + T_BYTES;

        #pragma unroll
        for (int ks = 0; ks < 4; ks++) {
            const int kb = ks * 8 + kcol;
            // B fragments: 8 n-tiles x 2 regs
            uint32_t bf[8][2];
            #pragma unroll
            for (int ni = 0; ni < 8; ni++) {
                int br = brow_base + ni * 8;
                bf[ni][0] = lds32(stB + sw128((uint32_t)(br * 128 + kb * 4)));
                bf[ni][1] = lds32(stB + sw128((uint32_t)(br * 128 + (kb + 4) * 4)));
            }
            // A fragments: 2 m-tiles x 4 regs (cvt.rna to tf32 — A is raw fp32)
            #pragma unroll
            for (int mi = 0; mi < 2; mi++) {
                int ar = arow_base + mi * 16;
                uint32_t af[4];
                af[0] = rna_tf32_u(lds32(stA + sw128((uint32_t)(ar * 128 + kb * 4))));
                af[1] = rna_tf32_u(lds32(stA + sw128((uint32_t)((ar + 8) * 128 + kb * 4))));
                af[2] = rna_tf32_u(lds32(stA + sw128((uint32_t)(ar * 128 + (kb + 4) * 4))));
                af[3] = rna_tf32_u(lds32(stA + sw128((uint32_t)((ar + 8) * 128 + (kb + 4) * 4))));
                #pragma unroll
                for (int ni = 0; ni < 8; ni++) mma_tf32(acc[mi][ni], af, bf[ni]);
            }
        }
        __syncthreads();
        if (kt + NST - 1 < KT) load_stage(kt + NST - 1);
    }

    // ---------------- epilogue ----------------
    #pragma unroll
    for (int mi = 0; mi < 2; mi++) {
        const int r0 = wm * 32 + mi * 16 + (lane >> 2);
        const size_t i0 = mrow0 + r0;
        const float dis0 = g_dis[i0], dis1 = g_dis[i0 + 8];
        #pragma unroll
        for (int ni = 0; ni < 8; ni++) {
            const int n = (int)nrow0 + wn * 64 + ni * 8 + (lane & 3) * 2;
            if (EPI == 0) {
                g_Mt[(size_t)n * NN + i0]           = rna_tf32(dis0 * acc[mi][ni][0]);
                g_Mt[(size_t)(n + 1) * NN + i0]     = rna_tf32(dis0 * acc[mi][ni][1]);
                g_Mt[(size_t)n * NN + i0 + 8]       = rna_tf32(dis1 * acc[mi][ni][2]);
                g_Mt[(size_t)(n + 1) * NN + i0 + 8] = rna_tf32(dis1 * acc[mi][ni][3]);
            } else {
                const float b0 = bias[n], b1 = bias[n + 1];
                float v0 = dis0 * (acc[mi][ni][0] + g_Mt[(size_t)n * NN + i0]) + b0;
                float v1 = dis0 * (acc[mi][ni][1] + g_Mt[(size_t)(n + 1) * NN + i0]) + b1;
                float v2 = dis1 * (acc[mi][ni][2] + g_Mt[(size_t)n * NN + i0 + 8]) + b0;
                float v3 = dis1 * (acc[mi][ni][3] + g_Mt[(size_t)(n + 1) * NN + i0 + 8]) + b1;
                float2 p0 = make_float2(v0 > 0.f ? v0 : 0.f, v1 > 0.f ? v1 : 0.f);
                float2 p1 = make_float2(v2 > 0.f ? v2 : 0.f, v3 > 0.f ? v3 : 0.f);
                *reinterpret_cast<float2*>(out + i0 * DIM + n)       = p0;
                *reinterpret_cast<float2*>(out + (i0 + 8) * DIM + n) = p1;
            }
        }
    }
}

// ---------------- launch ----------------
extern "C" void kernel_launch(void* const* d_in, const int* in_sizes, int n_in,
                              void* d_out, int out_size) {
    const float* x   = (const float*)d_in[0];
    const float* adj = (const float*)d_in[1];
    const float* W   = (const float*)d_in[2];
    const float* b   = (const float*)d_in[3];
    float* out = (float*)d_out;

    cudaFuncSetAttribute(gemm_k<0>, cudaFuncAttributeMaxDynamicSharedMemorySize, DSMEM);
    cudaFuncSetAttribute(gemm_k<1>, cudaFuncAttributeMaxDynamicSharedMemorySize, DSMEM);

    degree_kernel<<<NN, 256>>>(adj);
    prep_w_kernel<<<DIM, DIM>>>(W);
    gemm_k<0><<<dim3(NN / 128, 2), 256, DSMEM>>>(x, DIM, DIM / 32, nullptr, nullptr);
    gemm_k<1><<<dim3(NN / 128, 2), 256, DSMEM>>>(adj, NN, NN / 32, b, out);
}